// round 7
// baseline (speedup 1.0000x reference)
#include <cuda_runtime.h>

#define BB 32
#define LL 64
#define NPAIRS 2016          // L*(L-1)/2
#define NUNITS 41664         // sum_{l1=1}^{62} l1*(63-l1)
#define T3BLK 163            // ceil(NUNITS/256)
#define T2BLK 8              // ceil(NPAIRS/256)
#define KPB (T3BLK + T2BLK)  // 171 blocks per batch

// Cross-block reduction scratch (zero at module load; kernel self-resets,
// so every call — correctness, capture, each graph replay — sees zeros).
__device__ float    g_acc[BB];
__device__ unsigned g_cnt[BB];

// offs(l1) = sum_{m=1}^{l1-1} m*(63-m)  (exact integer closed form)
__device__ __forceinline__ int offs_fn(int l1) {
    int n = l1 - 1;
    int a = n * (n + 1);
    return (63 * a) / 2 - a * (2 * n + 1) / 6;
}

__global__ void __launch_bounds__(256) gp_kernel(
        const float* __restrict__ x,
        const float* __restrict__ th0,
        const float* __restrict__ th1,
        const float* __restrict__ th2,
        const float* __restrict__ th3,
        float* __restrict__ out) {
    const int bk  = blockIdx.x;
    const int b   = bk / KPB;
    const int k   = bk - b * KPB;
    const int tid = threadIdx.x;

    __shared__ float4 sx[LL];     // x_b, one float4 per position
    __shared__ int    so[LL];     // flattened one-hot offsets o = l*4+c
    __shared__ float  wsum[8];

    if (tid < LL) {
        float4 v = ((const float4*)x)[b * LL + tid];
        sx[tid] = v;
        int c = v.y > 0.5f ? 1 : (v.z > 0.5f ? 2 : (v.w > 0.5f ? 3 : 0));
        so[tid] = tid * 4 + c;
    }
    __syncthreads();

    float acc = 0.f;

    if (k < T3BLK) {
        // ---- order-3: one (l0,l1,l2) triple per thread ----
        const int u = k * 256 + tid;
        if (u < NUNITS) {
            // branchless binary search: largest l1 in [1,62] with offs(l1) <= u
            int lo = 1, hi = 62;
            #pragma unroll
            for (int it = 0; it < 6; it++) {
                int mid = (lo + hi + 1) >> 1;
                if (offs_fn(mid) <= u) lo = mid; else hi = mid - 1;
            }
            const int l1  = lo;
            const int r   = u - offs_fn(l1);
            const int len = 63 - l1;              // >= 1
            const int l0  = r / len;
            const int l2  = l1 + 1 + (r - l0 * len);

            const int base2 = so[l0] * 256 + so[l1];
            float4 rv = ((const float4*)th3)[(size_t)base2 * 64 + l2];
            float4 xv = sx[l2];
            acc = fmaf(rv.x, xv.x, fmaf(rv.y, xv.y,
                  fmaf(rv.z, xv.z, rv.w * xv.w)));
        }
    } else {
        // ---- order-2: one pair per thread ----
        const int p = (k - T3BLK) * 256 + tid;
        if (p < NPAIRS) {
            int l1 = (int)((1.0f + sqrtf(8.0f * (float)p + 1.0f)) * 0.5f);
            if ((l1 * (l1 - 1)) >> 1 > p) l1--;
            if (((l1 + 1) * l1) >> 1 <= p) l1++;
            const int l0 = p - ((l1 * (l1 - 1)) >> 1);
            acc = th2[so[l0] * 256 + so[l1]];
        }
        // ---- order 0 + 1, folded into the first theta2 block ----
        if (k == T3BLK && tid < LL) {
            acc += th1[so[tid]];
            if (tid == 0) acc += th0[0];
        }
    }

    // intra-block reduction
    #pragma unroll
    for (int off = 16; off > 0; off >>= 1)
        acc += __shfl_xor_sync(0xffffffffu, acc, off);
    const int warp = tid >> 5;
    if ((tid & 31) == 0) wsum[warp] = acc;
    __syncthreads();

    // cross-block: atomicAdd partial; last block for this batch finalizes
    if (tid == 0) {
        float t = 0.f;
        #pragma unroll
        for (int wi = 0; wi < 8; wi++) t += wsum[wi];
        atomicAdd(&g_acc[b], t);
        __threadfence();
        unsigned done = atomicAdd(&g_cnt[b], 1u);
        if (done == KPB - 1) {
            __threadfence();
            out[b] = g_acc[b];
            g_acc[b] = 0.f;      // reset for next replay
            g_cnt[b] = 0u;
        }
    }
}

extern "C" void kernel_launch(void* const* d_in, const int* in_sizes, int n_in,
                              void* d_out, int out_size) {
    const float* x   = (const float*)d_in[0];   // (B, L*C) one-hot
    const float* th0 = (const float*)d_in[1];   // (1,)
    const float* th1 = (const float*)d_in[2];   // (L, C)
    const float* th2 = (const float*)d_in[3];   // (L*C, L*C)
    const float* th3 = (const float*)d_in[4];   // (L*C, L*C, L*C)
    float* out = (float*)d_out;                 // (B, 1)

    gp_kernel<<<BB * KPB, 256>>>(x, th0, th1, th2, th3, out);
}

// round 8
// speedup vs baseline: 1.3113x; 1.3113x over previous
#include <cuda_runtime.h>

#define BB 32
#define BG 8                 // batches per thread
#define NBG (BB / BG)        // 4 batch groups
#define LL 64
#define NPAIRS 2016          // L*(L-1)/2
#define NUNITS 41664         // sum_{l1=1}^{62} l1*(63-l1)
#define T3BLK 163            // ceil(NUNITS/256)
#define T2BLK 8              // ceil(NPAIRS/256)
#define KPB (T3BLK + T2BLK)  // 171 blocks per batch-group

// Cross-block reduction scratch (zero at module load; kernel self-resets,
// so every call — correctness, capture, each graph replay — sees zeros).
__device__ float    g_acc[BB];
__device__ unsigned g_cnt[NBG];

// offs(l1) = sum_{m=1}^{l1-1} m*(63-m)  (exact integer closed form)
__device__ __forceinline__ int offs_fn(int l1) {
    int n = l1 - 1;
    int a = n * (n + 1);
    return (63 * a) / 2 - a * (2 * n + 1) / 6;
}

__global__ void __launch_bounds__(256) gp_kernel(
        const float* __restrict__ x,
        const float* __restrict__ th0,
        const float* __restrict__ th1,
        const float* __restrict__ th2,
        const float* __restrict__ th3,
        float* __restrict__ out) {
    const int g   = blockIdx.x / KPB;        // batch group [0,4)
    const int k   = blockIdx.x - g * KPB;    // block role within group
    const int tid = threadIdx.x;

    __shared__ float4 sx[BG][LL];    // x for 8 batches
    __shared__ int    so[BG][LL];    // one-hot offsets o = l*4+c per batch
    __shared__ int    soff[63];      // offs(l1) prefix table
    __shared__ float  wsum[8][BG];   // per-warp, per-batch partials

    // fill x/offset tables for the 8 batches of this group
    for (int idx = tid; idx < BG * LL; idx += 256) {
        int j = idx >> 6, l = idx & 63;
        float4 v = ((const float4*)x)[(g * BG + j) * LL + l];
        sx[j][l] = v;
        int c = v.y > 0.5f ? 1 : (v.z > 0.5f ? 2 : (v.w > 0.5f ? 3 : 0));
        so[j][l] = l * 4 + c;
    }
    if (tid >= 1 && tid < 63) soff[tid] = offs_fn(tid);
    __syncthreads();

    float acc[BG];
    #pragma unroll
    for (int j = 0; j < BG; j++) acc[j] = 0.f;

    if (k < T3BLK) {
        // ---- order-3: one (l0,l1,l2) triple per thread, 8 batches ----
        const int u = k * 256 + tid;
        if (u < NUNITS) {
            // largest l1 in [1,62] with offs(l1) <= u  (smem binary search)
            int lo = 1, hi = 62;
            #pragma unroll
            for (int it = 0; it < 6; it++) {
                int mid = (lo + hi + 1) >> 1;
                if (soff[mid] <= u) lo = mid; else hi = mid - 1;
            }
            const int l1  = lo;
            const int r   = u - soff[l1];
            const int len = 63 - l1;                 // >= 1
            const int l0  = r / len;
            const int l2  = l1 + 1 + (r - l0 * len);

            const float4* __restrict__ t3 = (const float4*)th3;
            #pragma unroll
            for (int j = 0; j < BG; j++) {
                const int base2 = so[j][l0] * 256 + so[j][l1];
                float4 rv = t3[(size_t)base2 * 64 + l2];
                float4 xv = sx[j][l2];
                acc[j] = fmaf(rv.x, xv.x, fmaf(rv.y, xv.y,
                         fmaf(rv.z, xv.z, rv.w * xv.w)));
            }
        }
    } else {
        // ---- order-2: one pair per thread, 8 batches ----
        const int p = (k - T3BLK) * 256 + tid;
        if (p < NPAIRS) {
            int l1 = (int)((1.0f + sqrtf(8.0f * (float)p + 1.0f)) * 0.5f);
            if ((l1 * (l1 - 1)) >> 1 > p) l1--;
            if (((l1 + 1) * l1) >> 1 <= p) l1++;
            const int l0 = p - ((l1 * (l1 - 1)) >> 1);
            #pragma unroll
            for (int j = 0; j < BG; j++)
                acc[j] = th2[so[j][l0] * 256 + so[j][l1]];
        }
        // ---- order 0 + 1, folded into the first theta2 block ----
        if (k == T3BLK && tid < LL) {
            #pragma unroll
            for (int j = 0; j < BG; j++) {
                acc[j] += th1[so[j][tid]];
                if (tid == 0) acc[j] += th0[0];
            }
        }
    }

    // intra-warp butterfly on each batch accumulator
    #pragma unroll
    for (int j = 0; j < BG; j++) {
        #pragma unroll
        for (int off = 16; off > 0; off >>= 1)
            acc[j] += __shfl_xor_sync(0xffffffffu, acc[j], off);
    }
    const int warp = tid >> 5;
    if ((tid & 31) == 0) {
        #pragma unroll
        for (int j = 0; j < BG; j++) wsum[warp][j] = acc[j];
    }
    __syncthreads();

    // 8 threads: sum 8 warps for one batch each, atomicAdd to global
    if (tid < BG) {
        float t = 0.f;
        #pragma unroll
        for (int w = 0; w < 8; w++) t += wsum[w][tid];
        atomicAdd(&g_acc[g * BG + tid], t);
        __threadfence();
    }
    __syncthreads();

    // last block of this group finalizes its 8 outputs
    if (tid == 0) {
        unsigned done = atomicAdd(&g_cnt[g], 1u);
        if (done == KPB - 1) {
            __threadfence();
            #pragma unroll
            for (int j = 0; j < BG; j++) {
                int bidx = g * BG + j;
                out[bidx] = g_acc[bidx];
                g_acc[bidx] = 0.f;       // reset for next replay
            }
            g_cnt[g] = 0u;
        }
    }
}

extern "C" void kernel_launch(void* const* d_in, const int* in_sizes, int n_in,
                              void* d_out, int out_size) {
    const float* x   = (const float*)d_in[0];   // (B, L*C) one-hot
    const float* th0 = (const float*)d_in[1];   // (1,)
    const float* th1 = (const float*)d_in[2];   // (L, C)
    const float* th2 = (const float*)d_in[3];   // (L*C, L*C)
    const float* th3 = (const float*)d_in[4];   // (L*C, L*C, L*C)
    float* out = (float*)d_out;                 // (B, 1)

    gp_kernel<<<NBG * KPB, 256>>>(x, th0, th1, th2, th3, out);
}

// round 9
// speedup vs baseline: 1.3860x; 1.0570x over previous
#include <cuda_runtime.h>

#define BB 32
#define LL 64
#define NPAIRS 2016          // L*(L-1)/2
#define CHUNKS 16            // blocks per batch
#define HALF 1024            // pair-slots per half

// Cross-block reduction scratch (zero at module load; kernel self-resets,
// so every call — correctness, capture, each graph replay — sees zeros).
__device__ float    g_acc[BB];
__device__ unsigned g_cnt[BB];

__device__ __forceinline__ void decode_pair(int p, int& l0, int& l1) {
    l1 = (int)((1.0f + sqrtf(8.0f * (float)p + 1.0f)) * 0.5f);
    if ((l1 * (l1 - 1)) >> 1 > p) l1--;
    if (((l1 + 1) * l1) >> 1 <= p) l1++;
    l0 = p - ((l1 * (l1 - 1)) >> 1);
}

__global__ void __launch_bounds__(256) gp_kernel(
        const float* __restrict__ x,
        const float* __restrict__ th0,
        const float* __restrict__ th1,
        const float* __restrict__ th2,
        const float* __restrict__ th3,
        float* __restrict__ out) {
    const int b     = blockIdx.x >> 4;       // / CHUNKS
    const int chunk = blockIdx.x & 15;       // % CHUNKS
    const int tid   = threadIdx.x;
    const int sub   = tid & 3;               // lane within 4-lane group
    const int grp   = tid >> 2;              // group in block [0,64)
    const int w     = grp >> 3;              // warp [0,8)
    const int gi    = grp & 7;               // group in warp [0,8)
    // balanced slot map: within-warp consecutive, warp/chunk strided
    const int slot  = w * 128 + chunk * 8 + gi;   // [0,1024)
    const int pA    = slot;                  // long strips (l1 <= ~45)
    const int pB    = slot + HALF;           // short strips (l1 >= ~45)
    const bool pBv  = (pB < NPAIRS);

    __shared__ float4 sx[LL];
    __shared__ int    so[LL];
    __shared__ float  wsum[8];

    if (tid < LL) {
        float4 v = ((const float4*)x)[b * LL + tid];
        sx[tid] = v;
        int c = v.y > 0.5f ? 1 : (v.z > 0.5f ? 2 : (v.w > 0.5f ? 3 : 0));
        so[tid] = tid * 4 + c;
    }
    __syncthreads();

    int l0A, l1A, l0B, l1B;
    decode_pair(pA, l0A, l1A);
    decode_pair(pB, l0B, l1B);
    if (!pBv) { l0B = 0; l1B = 0; }          // keep smem indices in range

    const int base2A = so[l0A] * 256 + so[l1A];
    const int base2B = so[l0B] * 256 + so[l1B];

    // early independent order-2 loads
    float t2 = (sub == 0) ? th2[base2A] : 0.f;
    if (pBv && sub == 0) t2 += th2[base2B];

    const float4* __restrict__ rowA = (const float4*)th3 + (size_t)base2A * 64;
    const float4* __restrict__ rowB = (const float4*)th3 + (size_t)base2B * 64;

    float accA = 0.f, accB = 0.f;
    int l2A = l1A + 1 + sub;
    int l2B = l1B + 1 + sub;

    #pragma unroll 4
    for (int t = 0; t < 16; t++) {
        if (l2A < LL) {
            float4 r  = rowA[l2A];
            float4 xv = sx[l2A];
            accA = fmaf(r.x, xv.x, fmaf(r.y, xv.y,
                   fmaf(r.z, xv.z, fmaf(r.w, xv.w, accA))));
        }
        if (pBv && l2B < LL) {
            float4 r  = rowB[l2B];
            float4 xv = sx[l2B];
            accB = fmaf(r.x, xv.x, fmaf(r.y, xv.y,
                   fmaf(r.z, xv.z, fmaf(r.w, xv.w, accB))));
        }
        l2A += 4;
        l2B += 4;
    }

    float acc = accA + accB + t2;

    // order 0 + 1, folded into chunk-0 blocks (first 64 threads)
    if (chunk == 0 && tid < LL) {
        acc += th1[so[tid]];
        if (tid == 0) acc += th0[0];
    }

    // intra-block reduction
    #pragma unroll
    for (int off = 16; off > 0; off >>= 1)
        acc += __shfl_xor_sync(0xffffffffu, acc, off);
    const int warp = tid >> 5;
    if ((tid & 31) == 0) wsum[warp] = acc;
    __syncthreads();

    // cross-block: atomicAdd partial; last block for this batch finalizes
    if (tid == 0) {
        float t = 0.f;
        #pragma unroll
        for (int wi = 0; wi < 8; wi++) t += wsum[wi];
        atomicAdd(&g_acc[b], t);
        __threadfence();
        unsigned done = atomicAdd(&g_cnt[b], 1u);
        if (done == CHUNKS - 1) {
            __threadfence();
            out[b] = g_acc[b];
            g_acc[b] = 0.f;      // reset for next replay
            g_cnt[b] = 0u;
        }
    }
}

extern "C" void kernel_launch(void* const* d_in, const int* in_sizes, int n_in,
                              void* d_out, int out_size) {
    const float* x   = (const float*)d_in[0];   // (B, L*C) one-hot
    const float* th0 = (const float*)d_in[1];   // (1,)
    const float* th1 = (const float*)d_in[2];   // (L, C)
    const float* th2 = (const float*)d_in[3];   // (L*C, L*C)
    const float* th3 = (const float*)d_in[4];   // (L*C, L*C, L*C)
    float* out = (float*)d_out;                 // (B, 1)

    gp_kernel<<<BB * CHUNKS, 256>>>(x, th0, th1, th2, th3, out);
}

// round 10
// speedup vs baseline: 1.5923x; 1.1488x over previous
#include <cuda_runtime.h>

#define BB 32
#define LL 64
#define NPAIRS 2016          // L*(L-1)/2
#define CHUNKS 32            // blocks per batch

// Cross-block reduction scratch (zero at module load; kernel self-resets,
// so every call — correctness, capture, each graph replay — sees zeros).
__device__ float    g_acc[BB];
__device__ unsigned g_cnt[BB];

__global__ void __launch_bounds__(256) gp_kernel(
        const float* __restrict__ x,
        const float* __restrict__ th0,
        const float* __restrict__ th1,
        const float* __restrict__ th2,
        const float* __restrict__ th3,
        float* __restrict__ out) {
    const int b     = blockIdx.x >> 5;       // / CHUNKS
    const int chunk = blockIdx.x & 31;       // % CHUNKS
    const int tid   = threadIdx.x;
    const int sub   = tid & 3;               // lane within 4-lane group
    const int grp   = tid >> 2;              // group in block [0,64)
    const int w     = grp >> 3;              // warp [0,8)
    const int gi    = grp & 7;               // group-slot in warp [0,8)
    // balanced map: consecutive pairs within a warp (uniform trip count),
    // warps/chunks strided across the full l1 range (block/SM balance)
    const int p     = w * 256 + chunk * 8 + gi;   // [0,2048)

    __shared__ int   so_s[LL];    // flattened one-hot offsets o = l*4+c
    __shared__ float wsum[8];

    if (tid < LL) {
        float4 v = ((const float4*)x)[b * LL + tid];
        int c = v.y > 0.5f ? 1 : (v.z > 0.5f ? 2 : (v.w > 0.5f ? 3 : 0));
        so_s[tid] = tid * 4 + c;
    }
    __syncthreads();

    float acc = 0.f;

    if (p < NPAIRS) {
        // branchless decode: p = l1*(l1-1)/2 + l0, l0 < l1
        int l1 = (int)((1.0f + sqrtf(8.0f * (float)p + 1.0f)) * 0.5f);
        if ((l1 * (l1 - 1)) >> 1 > p) l1--;
        if (((l1 + 1) * l1) >> 1 <= p) l1++;
        const int l0 = p - ((l1 * (l1 - 1)) >> 1);

        const int base2 = so_s[l0] * 256 + so_s[l1];
        float t2 = (sub == 0) ? th2[base2] : 0.f;     // order-2 term

        const float* __restrict__ row = th3 + (size_t)base2 * 256;
        const int l2b = l1 + 1 + sub;

        // one-hot dot == scalar selection: row[so[l2]].
        // Fully unrolled + predicated: all 16 gathers are independent,
        // addresses computable up-front -> max loads in flight.
        float a0 = 0.f, a1 = 0.f;
        #pragma unroll
        for (int t = 0; t < 8; t++) {
            int i = l2b + 4 * t;
            if (i < LL) a0 += row[so_s[i]];
        }
        #pragma unroll
        for (int t = 8; t < 16; t++) {
            int i = l2b + 4 * t;
            if (i < LL) a1 += row[so_s[i]];
        }
        acc = a0 + a1 + t2;
    }

    // order 0 + 1, folded into chunk-0 blocks (first 64 threads)
    if (chunk == 0 && tid < LL) {
        acc += th1[so_s[tid]];
        if (tid == 0) acc += th0[0];
    }

    // intra-block reduction
    #pragma unroll
    for (int off = 16; off > 0; off >>= 1)
        acc += __shfl_xor_sync(0xffffffffu, acc, off);
    const int warp = tid >> 5;
    if ((tid & 31) == 0) wsum[warp] = acc;
    __syncthreads();

    // cross-block: atomicAdd partial; last block for this batch finalizes
    if (tid == 0) {
        float t = 0.f;
        #pragma unroll
        for (int wi = 0; wi < 8; wi++) t += wsum[wi];
        atomicAdd(&g_acc[b], t);
        __threadfence();
        unsigned done = atomicAdd(&g_cnt[b], 1u);
        if (done == CHUNKS - 1) {
            __threadfence();
            out[b] = g_acc[b];
            g_acc[b] = 0.f;      // reset for next replay
            g_cnt[b] = 0u;
        }
    }
}

extern "C" void kernel_launch(void* const* d_in, const int* in_sizes, int n_in,
                              void* d_out, int out_size) {
    const float* x   = (const float*)d_in[0];   // (B, L*C) one-hot
    const float* th0 = (const float*)d_in[1];   // (1,)
    const float* th1 = (const float*)d_in[2];   // (L, C)
    const float* th2 = (const float*)d_in[3];   // (L*C, L*C)
    const float* th3 = (const float*)d_in[4];   // (L*C, L*C, L*C)
    float* out = (float*)d_out;                 // (B, 1)

    gp_kernel<<<BB * CHUNKS, 256>>>(x, th0, th1, th2, th3, out);
}